// round 1
// baseline (speedup 1.0000x reference)
#include <cuda_runtime.h>
#include <math.h>

#define NROWS 200000
#define DIN   512
#define DOUT  128
#define CHUNK 512
#define NB    ((NROWS + CHUNK - 1) / CHUNK)   // 391 partial blocks

// ---- scratch (device globals; no runtime allocation) ----
__device__ float g_Q[(size_t)NROWS * DOUT];
__device__ float g_K[(size_t)NROWS * DOUT];
__device__ float g_V[(size_t)NROWS * DOUT];
__device__ float g_KVpart[(size_t)NB * DOUT * DOUT];
__device__ float g_kspart[(size_t)NB * DOUT];
__device__ float g_KV[DOUT * DOUT];
__device__ float g_ksum[DOUT];

__device__ __forceinline__ float elu_p1(float x) {
    // elu(x) + 1
    return x > 0.0f ? x + 1.0f : expf(x);
}

// ============================================================================
// Kernel A: Q,K,V = f(h @ W) for W in {Wq, Wk, Wv}.
// Grid: (NROWS/64, 3). Block: 256 threads. Tile: 64x128 out, BK=16.
// Each thread: 4x8 micro-tile, fp32 accumulation.
// ============================================================================
__global__ __launch_bounds__(256) void qkv_kernel(
    const float* __restrict__ h,
    const float* __restrict__ Wq,
    const float* __restrict__ Wk,
    const float* __restrict__ Wv)
{
    __shared__ float As[16][68];    // k-major (transposed) A tile, padded: 272B row stride (16B mult)
    __shared__ float Bs[16][128];   // B tile

    const int which = blockIdx.y;
    const float* W;
    float* Out;
    if (which == 0)      { W = Wq; Out = g_Q; }
    else if (which == 1) { W = Wk; Out = g_K; }
    else                 { W = Wv; Out = g_V; }

    const int row0 = blockIdx.x * 64;
    const int tid  = threadIdx.x;
    const int cg   = tid & 15;        // col group -> 8 cols
    const int rg   = tid >> 4;        // row group -> 4 rows
    const int mc   = cg * 8;
    const int mr   = rg * 4;

    float acc[4][8];
    #pragma unroll
    for (int i = 0; i < 4; i++)
        #pragma unroll
        for (int j = 0; j < 8; j++) acc[i][j] = 0.0f;

    // A-load mapping: 256 float4 = 64 rows x 4 float4
    const int la_r = tid >> 2;          // 0..63
    const int la_c = (tid & 3) * 4;     // 0,4,8,12
    const float* hptr = h + (size_t)(row0 + la_r) * DIN + la_c;

    // B-load mapping: 512 float4, 2 per thread
    const int kr0 = tid >> 5;                 // 0..7
    const int cq0 = (tid & 31) * 4;
    const int kr1 = ((tid + 256) >> 5);       // 8..15
    const int cq1 = cq0;

    for (int k0 = 0; k0 < DIN; k0 += 16) {
        float4 av  = *(const float4*)(hptr + k0);
        float4 bv0 = *(const float4*)(W + (size_t)(k0 + kr0) * DOUT + cq0);
        float4 bv1 = *(const float4*)(W + (size_t)(k0 + kr1) * DOUT + cq1);

        __syncthreads();   // previous iteration's compute done
        As[la_c + 0][la_r] = av.x;
        As[la_c + 1][la_r] = av.y;
        As[la_c + 2][la_r] = av.z;
        As[la_c + 3][la_r] = av.w;
        *(float4*)&Bs[kr0][cq0] = bv0;
        *(float4*)&Bs[kr1][cq1] = bv1;
        __syncthreads();

        #pragma unroll
        for (int kk = 0; kk < 16; kk++) {
            float4 a  = *(const float4*)&As[kk][mr];
            float4 b0 = *(const float4*)&Bs[kk][mc];
            float4 b1 = *(const float4*)&Bs[kk][mc + 4];
            float ar[4] = {a.x, a.y, a.z, a.w};
            float br[8] = {b0.x, b0.y, b0.z, b0.w, b1.x, b1.y, b1.z, b1.w};
            #pragma unroll
            for (int i = 0; i < 4; i++)
                #pragma unroll
                for (int j = 0; j < 8; j++)
                    acc[i][j] = fmaf(ar[i], br[j], acc[i][j]);
        }
    }

    const bool act = (which < 2);
    #pragma unroll
    for (int i = 0; i < 4; i++) {
        float v[8];
        #pragma unroll
        for (int j = 0; j < 8; j++)
            v[j] = act ? elu_p1(acc[i][j]) : acc[i][j];
        float* orow = Out + (size_t)(row0 + mr + i) * DOUT + mc;
        *(float4*)(orow)     = make_float4(v[0], v[1], v[2], v[3]);
        *(float4*)(orow + 4) = make_float4(v[4], v[5], v[6], v[7]);
    }
}

// ============================================================================
// Kernel B: per-block partial KV = K_chunk^T @ V_chunk  (128x128), plus
// partial k_sum. Deterministic (no atomics). Grid: NB blocks x 256 threads.
// Each thread: 8x8 micro-tile.
// ============================================================================
__global__ __launch_bounds__(256) void kv_kernel()
{
    __shared__ float Ks[16][128];
    __shared__ float Vs[16][128];

    const int tid = threadIdx.x;
    const int cg  = tid & 15;
    const int rg  = tid >> 4;
    const int mc  = cg * 8;          // V feature cols
    const int mr  = rg * 8;          // K feature rows

    float acc[8][8];
    #pragma unroll
    for (int i = 0; i < 8; i++)
        #pragma unroll
        for (int j = 0; j < 8; j++) acc[i][j] = 0.0f;
    float ksum_local = 0.0f;

    const int base = blockIdx.x * CHUNK;

    const int kr0 = tid >> 5;               // 0..7
    const int cq  = (tid & 31) * 4;
    const int kr1 = (tid + 256) >> 5;       // 8..15

    for (int t = 0; t < CHUNK; t += 16) {
        const int ra = base + t + kr0;
        const int rb = base + t + kr1;
        float4 k0 = make_float4(0, 0, 0, 0), k1 = k0, v0 = k0, v1 = k0;
        if (ra < NROWS) {
            k0 = *(const float4*)(g_K + (size_t)ra * DOUT + cq);
            v0 = *(const float4*)(g_V + (size_t)ra * DOUT + cq);
        }
        if (rb < NROWS) {
            k1 = *(const float4*)(g_K + (size_t)rb * DOUT + cq);
            v1 = *(const float4*)(g_V + (size_t)rb * DOUT + cq);
        }
        __syncthreads();
        *(float4*)&Ks[kr0][cq] = k0;
        *(float4*)&Ks[kr1][cq] = k1;
        *(float4*)&Vs[kr0][cq] = v0;
        *(float4*)&Vs[kr1][cq] = v1;
        __syncthreads();

        #pragma unroll
        for (int kk = 0; kk < 16; kk++) {
            float4 ka0 = *(const float4*)&Ks[kk][mr];
            float4 ka1 = *(const float4*)&Ks[kk][mr + 4];
            float4 vb0 = *(const float4*)&Vs[kk][mc];
            float4 vb1 = *(const float4*)&Vs[kk][mc + 4];
            float kr[8] = {ka0.x, ka0.y, ka0.z, ka0.w, ka1.x, ka1.y, ka1.z, ka1.w};
            float vr[8] = {vb0.x, vb0.y, vb0.z, vb0.w, vb1.x, vb1.y, vb1.z, vb1.w};
            #pragma unroll
            for (int i = 0; i < 8; i++)
                #pragma unroll
                for (int j = 0; j < 8; j++)
                    acc[i][j] = fmaf(kr[i], vr[j], acc[i][j]);
        }

        if (tid < DOUT) {
            #pragma unroll
            for (int kk = 0; kk < 16; kk++)
                ksum_local += Ks[kk][tid];
        }
    }

    float* kvout = g_KVpart + (size_t)blockIdx.x * (DOUT * DOUT);
    #pragma unroll
    for (int i = 0; i < 8; i++) {
        float* row = kvout + (size_t)(mr + i) * DOUT + mc;
        *(float4*)(row)     = make_float4(acc[i][0], acc[i][1], acc[i][2], acc[i][3]);
        *(float4*)(row + 4) = make_float4(acc[i][4], acc[i][5], acc[i][6], acc[i][7]);
    }
    if (tid < DOUT)
        g_kspart[(size_t)blockIdx.x * DOUT + tid] = ksum_local;
}

// ============================================================================
// Reduce partials -> g_KV, g_ksum. (16384 + 128 outputs)
// ============================================================================
__global__ void reduce_kernel()
{
    const int i = blockIdx.x * blockDim.x + threadIdx.x;
    if (i < DOUT * DOUT) {
        float s = 0.0f;
        for (int b = 0; b < NB; b++)
            s += g_KVpart[(size_t)b * (DOUT * DOUT) + i];
        g_KV[i] = s;
    } else {
        const int j = i - DOUT * DOUT;
        if (j < DOUT) {
            float s = 0.0f;
            for (int b = 0; b < NB; b++)
                s += g_kspart[(size_t)b * DOUT + j];
            g_ksum[j] = s;
        }
    }
}

// ============================================================================
// Kernel C: out = elu((Q @ KV) * (1 / (Q @ ksum)))
// Grid: NROWS/64 blocks x 256 threads. KV + transposed Q tile fully in smem.
// Dynamic smem: 16384 (KV) + 128*68 (Qt) + 128 (ksum) + 64 (z) floats.
// ============================================================================
#define SMEMC_FLOATS (DOUT * DOUT + DOUT * 68 + DOUT + 64)

__global__ __launch_bounds__(256) void out_kernel(float* __restrict__ out)
{
    extern __shared__ float sm[];
    float* KVs    = sm;                       // [128][128]
    float* Qs     = sm + DOUT * DOUT;         // [128][68]  (k-major transposed Q tile)
    float* ksum_s = Qs + DOUT * 68;           // [128]
    float* z_s    = ksum_s + DOUT;            // [64]

    const int tid  = threadIdx.x;
    const int row0 = blockIdx.x * 64;

    // stage KV (4096 float4, 16 per thread)
    for (int i = tid; i < (DOUT * DOUT) / 4; i += 256)
        ((float4*)KVs)[i] = ((const float4*)g_KV)[i];
    if (tid < DOUT)
        ksum_s[tid] = g_ksum[tid];

    // stage Q tile transposed: 2048 float4
    for (int i = tid; i < 2048; i += 256) {
        const int r  = i >> 5;            // 0..63
        const int cq = (i & 31) * 4;      // 0..124
        float4 q = *(const float4*)(g_Q + (size_t)(row0 + r) * DOUT + cq);
        Qs[(cq + 0) * 68 + r] = q.x;
        Qs[(cq + 1) * 68 + r] = q.y;
        Qs[(cq + 2) * 68 + r] = q.z;
        Qs[(cq + 3) * 68 + r] = q.w;
    }
    __syncthreads();

    if (tid < 64) {
        float dot = 0.0f;
        #pragma unroll 8
        for (int k = 0; k < DOUT; k++)
            dot = fmaf(Qs[k * 68 + tid], ksum_s[k], dot);
        z_s[tid] = 1.0f / dot;
    }
    __syncthreads();

    const int cg = tid & 15;
    const int rg = tid >> 4;
    const int mc = cg * 8;
    const int mr = rg * 4;

    float acc[4][8];
    #pragma unroll
    for (int i = 0; i < 4; i++)
        #pragma unroll
        for (int j = 0; j < 8; j++) acc[i][j] = 0.0f;

    #pragma unroll 8
    for (int kk = 0; kk < DOUT; kk++) {
        float4 a  = *(const float4*)&Qs[kk * 68 + mr];
        float4 b0 = *(const float4*)&KVs[kk * DOUT + mc];
        float4 b1 = *(const float4*)&KVs[kk * DOUT + mc + 4];
        float ar[4] = {a.x, a.y, a.z, a.w};
        float br[8] = {b0.x, b0.y, b0.z, b0.w, b1.x, b1.y, b1.z, b1.w};
        #pragma unroll
        for (int i = 0; i < 4; i++)
            #pragma unroll
            for (int j = 0; j < 8; j++)
                acc[i][j] = fmaf(ar[i], br[j], acc[i][j]);
    }

    #pragma unroll
    for (int i = 0; i < 4; i++) {
        const float z = z_s[mr + i];
        float v[8];
        #pragma unroll
        for (int j = 0; j < 8; j++) {
            float x = acc[i][j] * z;
            v[j] = x > 0.0f ? x : expm1f(x);   // elu
        }
        float* orow = out + (size_t)(row0 + mr + i) * DOUT + mc;
        *(float4*)(orow)     = make_float4(v[0], v[1], v[2], v[3]);
        *(float4*)(orow + 4) = make_float4(v[4], v[5], v[6], v[7]);
    }
}

// ============================================================================
// Launch
// ============================================================================
extern "C" void kernel_launch(void* const* d_in, const int* in_sizes, int n_in,
                              void* d_out, int out_size)
{
    const float* h  = (const float*)d_in[0];
    const float* Wq = (const float*)d_in[1];
    const float* Wk = (const float*)d_in[2];
    const float* Wv = (const float*)d_in[3];
    float* out = (float*)d_out;

    const int smemC = SMEMC_FLOATS * (int)sizeof(float);
    cudaFuncSetAttribute(out_kernel, cudaFuncAttributeMaxDynamicSharedMemorySize, smemC);

    dim3 gridA(NROWS / 64, 3);
    qkv_kernel<<<gridA, 256>>>(h, Wq, Wk, Wv);

    kv_kernel<<<NB, 256>>>();

    reduce_kernel<<<(DOUT * DOUT + DOUT + 255) / 256, 256>>>();

    out_kernel<<<NROWS / 64, 256, smemC>>>(out);
}

// round 3
// speedup vs baseline: 2.3078x; 2.3078x over previous
#include <cuda_runtime.h>
#include <cuda_bf16.h>
#include <math.h>
#include <stdint.h>

#define NROWS 200000
#define DIN   512
#define DOUT  128
#define NQKV  384
#define BK    32
#define NCHUNKS (DIN / BK)                 // 16
#define MTILE 128
#define NBLK_M ((NROWS + MTILE - 1) / MTILE)   // 1563

#define CHUNK 512
#define NB    ((NROWS + CHUNK - 1) / CHUNK)    // 391

// ---- scratch (device globals; no runtime allocation) ----
__device__ float g_Q[(size_t)NROWS * DOUT];
__device__ float g_K[(size_t)NROWS * DOUT];
__device__ float g_V[(size_t)NROWS * DOUT];
__device__ float g_KVpart[(size_t)NB * DOUT * DOUT];
__device__ float g_kspart[(size_t)NB * DOUT];
__device__ float g_KV[DOUT * DOUT];
__device__ float g_ksum[DOUT];

// split-bf16 weights, row-major [k][384] (n = which*128 + col)
__device__ __nv_bfloat16 g_Wb_hi[(size_t)DIN * NQKV];
__device__ __nv_bfloat16 g_Wb_lo[(size_t)DIN * NQKV];

// ---- qkv smem layout (dynamic) ----
// A: [stage][part][128 rows x 80B]   (BK=32 bf16 = 64B data + 16B pad)
// B: [stage][part][32 rows  x 272B]  (128 bf16 = 256B data + 16B pad)
#define A_ROW_B   80
#define A_PART_B  (MTILE * A_ROW_B)        // 10240
#define A_STAGE_B (2 * A_PART_B)           // 20480
#define B_ROW_B   272
#define B_PART_B  (BK * B_ROW_B)           // 8704
#define B_STAGE_B (2 * B_PART_B)           // 17408
#define SM_B_OFF  (2 * A_STAGE_B)          // 40960
#define SM_QKV_TOTAL (SM_B_OFF + 2 * B_STAGE_B)  // 75776

static __device__ __forceinline__ uint32_t smem_u32(const void* p) {
    uint32_t a;
    asm("{ .reg .u64 t; cvta.to.shared.u64 t, %1; cvt.u32.u64 %0, t; }" : "=r"(a) : "l"(p));
    return a;
}

static __device__ __forceinline__ void cp16(uint32_t dst, const void* src) {
    asm volatile("cp.async.cg.shared.global [%0], [%1], 16;" :: "r"(dst), "l"(src) : "memory");
}
#define CP_COMMIT()  asm volatile("cp.async.commit_group;" ::: "memory")
#define CP_WAIT(N)   asm volatile("cp.async.wait_group %0;" :: "n"(N) : "memory")

static __device__ __forceinline__ void ldsm_x4(uint32_t* r, uint32_t addr) {
    asm volatile("ldmatrix.sync.aligned.m8n8.x4.shared.b16 {%0,%1,%2,%3}, [%4];"
                 : "=r"(r[0]), "=r"(r[1]), "=r"(r[2]), "=r"(r[3]) : "r"(addr));
}
static __device__ __forceinline__ void ldsm_x4_t(uint32_t* r, uint32_t addr) {
    asm volatile("ldmatrix.sync.aligned.m8n8.x4.trans.shared.b16 {%0,%1,%2,%3}, [%4];"
                 : "=r"(r[0]), "=r"(r[1]), "=r"(r[2]), "=r"(r[3]) : "r"(addr));
}
static __device__ __forceinline__ void mma16816(float* d, const uint32_t* a,
                                                const uint32_t* b) {
    asm volatile(
        "mma.sync.aligned.m16n8k16.row.col.f32.bf16.bf16.f32 "
        "{%0,%1,%2,%3}, {%4,%5,%6,%7}, {%8,%9}, {%0,%1,%2,%3};"
        : "+f"(d[0]), "+f"(d[1]), "+f"(d[2]), "+f"(d[3])
        : "r"(a[0]), "r"(a[1]), "r"(a[2]), "r"(a[3]), "r"(b[0]), "r"(b[1]));
}

__device__ __forceinline__ float elu_p1(float x) {
    return x > 0.0f ? x + 1.0f : expf(x);
}

// ============================================================================
// Kernel W: split-bf16 weight conversion into [k][384] hi/lo arrays.
// ============================================================================
__global__ void convert_w(const float* __restrict__ Wq,
                          const float* __restrict__ Wk,
                          const float* __restrict__ Wv)
{
    int idx = blockIdx.x * 256 + threadIdx.x;     // 512*384
    if (idx >= DIN * NQKV) return;
    int k = idx / NQKV;
    int n = idx % NQKV;
    const float* W = (n < 128) ? Wq : (n < 256) ? Wk : Wv;
    float x = W[(size_t)k * DOUT + (n & 127)];
    __nv_bfloat16 hi = __float2bfloat16(x);
    __nv_bfloat16 lo = __float2bfloat16(x - __bfloat162float(hi));
    g_Wb_hi[idx] = hi;
    g_Wb_lo[idx] = lo;
}

// ============================================================================
// Kernel A: [Q|K|V] = f(h @ W_which) via mma.sync bf16 3-pass split.
// Grid (3, 1563): which = blockIdx.x (fastest -> L2 reuse of h tile).
// Block 128x128, 8 warps (4x2), warp tile 32x64, BK=32 double-buffered.
// ============================================================================
__global__ __launch_bounds__(256, 1) void qkv_mma(const float* __restrict__ h)
{
    extern __shared__ __align__(256) unsigned char sm[];
    const uint32_t sbase = smem_u32(sm);

    const int which = blockIdx.x;
    const int row0  = blockIdx.y * MTILE;
    const int tid   = threadIdx.x;
    const int wid   = tid >> 5;
    const int lane  = tid & 31;

    const int wm = wid & 3;          // warp M index
    const int wn = wid >> 2;         // warp N index
    const int m0 = wm * 32;
    const int n0w = wn * 64;

    // A load/convert mapping: thread -> (row = tid>>1, seg = (tid&1)*16)
    const int arow = tid >> 1;
    const int aseg = (tid & 1) * 16;
    int lrow = row0 + arow;
    if (lrow >= NROWS) lrow = NROWS - 1;
    const float* hrow = h + (size_t)lrow * DIN + aseg;
    const uint32_t a_sts_off = (uint32_t)(arow * A_ROW_B + aseg * 2);

    // B cp.async mapping: 512 cp16 per part, 2 per thread per part
    const int nbase = which * 128;

    float acc[2][8][4];
    #pragma unroll
    for (int i = 0; i < 2; i++)
        #pragma unroll
        for (int j = 0; j < 8; j++)
            #pragma unroll
            for (int r = 0; r < 4; r++) acc[i][j][r] = 0.0f;

    // ldmatrix source addresses (per-lane constants)
    const int a_r = (lane & 7) + (lane & 8);           // row within m16 frag
    const int a_c = ((lane >> 4) & 1) * 8;             // k halfword offset
    const int b_k = (lane & 7) + (lane & 8);           // k row within k16
    const int b_n = ((lane >> 4) & 1) * 8;             // n halfword offset

    // ---- helpers as lambdas ----
    auto issue_B = [&](int c, int stage) {
        const size_t src_row0 = (size_t)(c * BK) * NQKV + nbase;
        #pragma unroll
        for (int p = 0; p < 2; p++) {
            const __nv_bfloat16* srcb = p ? g_Wb_lo : g_Wb_hi;
            uint32_t dstb = sbase + SM_B_OFF + stage * B_STAGE_B + p * B_PART_B;
            #pragma unroll
            for (int it = 0; it < 2; it++) {
                int idx = tid + it * 256;
                int r = idx >> 4, c16 = idx & 15;
                cp16(dstb + r * B_ROW_B + c16 * 16,
                     srcb + src_row0 + (size_t)r * NQKV + c16 * 8);
            }
        }
        CP_COMMIT();
    };

    // ---- prologue: A0 regs, B0 cp.async, A0 STS ----
    float4 v[4];
    #pragma unroll
    for (int j = 0; j < 4; j++) v[j] = *(const float4*)(hrow + 0 * BK + 4 * j);
    issue_B(0, 0);
    {
        uint32_t dst_hi = sbase + 0 * A_STAGE_B + 0 * A_PART_B + a_sts_off;
        uint32_t dst_lo = dst_hi + A_PART_B;
        uint32_t hi[8], lo[8];
        float f[16];
        #pragma unroll
        for (int j = 0; j < 4; j++) {
            f[4*j+0]=v[j].x; f[4*j+1]=v[j].y; f[4*j+2]=v[j].z; f[4*j+3]=v[j].w;
        }
        #pragma unroll
        for (int p = 0; p < 8; p++) {
            __nv_bfloat16 ha = __float2bfloat16(f[2*p]);
            __nv_bfloat16 hb = __float2bfloat16(f[2*p+1]);
            __nv_bfloat16 la = __float2bfloat16(f[2*p]   - __bfloat162float(ha));
            __nv_bfloat16 lb = __float2bfloat16(f[2*p+1] - __bfloat162float(hb));
            hi[p] = (uint32_t)__bfloat16_as_ushort(ha) | ((uint32_t)__bfloat16_as_ushort(hb) << 16);
            lo[p] = (uint32_t)__bfloat16_as_ushort(la) | ((uint32_t)__bfloat16_as_ushort(lb) << 16);
        }
        asm volatile("st.shared.v4.b32 [%0], {%1,%2,%3,%4};" :: "r"(dst_hi),
                     "r"(hi[0]),"r"(hi[1]),"r"(hi[2]),"r"(hi[3]));
        asm volatile("st.shared.v4.b32 [%0], {%1,%2,%3,%4};" :: "r"(dst_hi+16),
                     "r"(hi[4]),"r"(hi[5]),"r"(hi[6]),"r"(hi[7]));
        asm volatile("st.shared.v4.b32 [%0], {%1,%2,%3,%4};" :: "r"(dst_lo),
                     "r"(lo[0]),"r"(lo[1]),"r"(lo[2]),"r"(lo[3]));
        asm volatile("st.shared.v4.b32 [%0], {%1,%2,%3,%4};" :: "r"(dst_lo+16),
                     "r"(lo[4]),"r"(lo[5]),"r"(lo[6]),"r"(lo[7]));
    }

    for (int c = 0; c < NCHUNKS; c++) {
        const int stage = c & 1;

        if (c + 1 < NCHUNKS) {
            #pragma unroll
            for (int j = 0; j < 4; j++)
                v[j] = *(const float4*)(hrow + (c + 1) * BK + 4 * j);
            issue_B(c + 1, stage ^ 1);
            CP_WAIT(1);
        } else {
            CP_WAIT(0);
        }
        __syncthreads();   // B(c) arrived, A(c) STS visible

        // ---- compute chunk c: 2 ksteps ----
        const uint32_t Ab = sbase + stage * A_STAGE_B;
        const uint32_t Bb = sbase + SM_B_OFF + stage * B_STAGE_B;
        #pragma unroll
        for (int ks = 0; ks < 2; ks++) {
            const int k0 = ks * 16;
            uint32_t afr[2][2][4];   // [part][im][reg]
            #pragma unroll
            for (int p = 0; p < 2; p++)
                #pragma unroll
                for (int im = 0; im < 2; im++) {
                    uint32_t addr = Ab + p * A_PART_B +
                        (uint32_t)((m0 + im * 16 + a_r) * A_ROW_B + (k0 + a_c) * 2);
                    ldsm_x4(afr[p][im], addr);
                }
            uint32_t bfr[2][4][4];   // [part][jn][reg]
            #pragma unroll
            for (int p = 0; p < 2; p++)
                #pragma unroll
                for (int jn = 0; jn < 4; jn++) {
                    uint32_t addr = Bb + p * B_PART_B +
                        (uint32_t)((k0 + b_k) * B_ROW_B + (n0w + jn * 16 + b_n) * 2);
                    ldsm_x4_t(bfr[p][jn], addr);
                }
            #pragma unroll
            for (int im = 0; im < 2; im++)
                #pragma unroll
                for (int jn = 0; jn < 4; jn++) {
                    #pragma unroll
                    for (int half = 0; half < 2; half++) {
                        const int j = jn * 2 + half;
                        mma16816(acc[im][j], afr[0][im], &bfr[0][jn][half * 2]); // hi*hi
                        mma16816(acc[im][j], afr[0][im], &bfr[1][jn][half * 2]); // hi*lo
                        mma16816(acc[im][j], afr[1][im], &bfr[0][jn][half * 2]); // lo*hi
                    }
                }
        }

        // ---- convert & STS A(c+1) into other stage ----
        if (c + 1 < NCHUNKS) {
            uint32_t dst_hi = sbase + (stage ^ 1) * A_STAGE_B + a_sts_off;
            uint32_t dst_lo = dst_hi + A_PART_B;
            float f[16];
            #pragma unroll
            for (int j = 0; j < 4; j++) {
                f[4*j+0]=v[j].x; f[4*j+1]=v[j].y; f[4*j+2]=v[j].z; f[4*j+3]=v[j].w;
            }
            uint32_t hi[8], lo[8];
            #pragma unroll
            for (int p = 0; p < 8; p++) {
                __nv_bfloat16 ha = __float2bfloat16(f[2*p]);
                __nv_bfloat16 hb = __float2bfloat16(f[2*p+1]);
                __nv_bfloat16 la = __float2bfloat16(f[2*p]   - __bfloat162float(ha));
                __nv_bfloat16 lb = __float2bfloat16(f[2*p+1] - __bfloat162float(hb));
                hi[p] = (uint32_t)__bfloat16_as_ushort(ha) | ((uint32_t)__bfloat16_as_ushort(hb) << 16);
                lo[p] = (uint32_t)__bfloat16_as_ushort(la) | ((uint32_t)__bfloat16_as_ushort(lb) << 16);
            }
            asm volatile("st.shared.v4.b32 [%0], {%1,%2,%3,%4};" :: "r"(dst_hi),
                         "r"(hi[0]),"r"(hi[1]),"r"(hi[2]),"r"(hi[3]));
            asm volatile("st.shared.v4.b32 [%0], {%1,%2,%3,%4};" :: "r"(dst_hi+16),
                         "r"(hi[4]),"r"(hi[5]),"r"(hi[6]),"r"(hi[7]));
            asm volatile("st.shared.v4.b32 [%0], {%1,%2,%3,%4};" :: "r"(dst_lo),
                         "r"(lo[0]),"r"(lo[1]),"r"(lo[2]),"r"(lo[3]));
            asm volatile("st.shared.v4.b32 [%0], {%1,%2,%3,%4};" :: "r"(dst_lo+16),
                         "r"(lo[4]),"r"(lo[5]),"r"(lo[6]),"r"(lo[7]));
        }
    }

    // ---- epilogue ----
    float* Out = (which == 0) ? g_Q : (which == 1) ? g_K : g_V;
    const bool act = (which < 2);
    const int g = lane >> 2;
    const int t = lane & 3;

    #pragma unroll
    for (int im = 0; im < 2; im++) {
        const int r0 = row0 + m0 + im * 16 + g;
        const int r1 = r0 + 8;
        #pragma unroll
        for (int j = 0; j < 8; j++) {
            const int col = n0w + j * 8 + t * 2;
            float c0 = acc[im][j][0], c1 = acc[im][j][1];
            float c2 = acc[im][j][2], c3 = acc[im][j][3];
            if (act) {
                c0 = elu_p1(c0); c1 = elu_p1(c1);
                c2 = elu_p1(c2); c3 = elu_p1(c3);
            }
            if (r0 < NROWS) *(float2*)(Out + (size_t)r0 * DOUT + col) = make_float2(c0, c1);
            if (r1 < NROWS) *(float2*)(Out + (size_t)r1 * DOUT + col) = make_float2(c2, c3);
        }
    }
}

// ============================================================================
// Kernel B: per-block partial KV = K_chunk^T @ V_chunk, plus partial k_sum.
// ============================================================================
__global__ __launch_bounds__(256) void kv_kernel()
{
    __shared__ float Ks[16][128];
    __shared__ float Vs[16][128];

    const int tid = threadIdx.x;
    const int cg  = tid & 15;
    const int rg  = tid >> 4;
    const int mc  = cg * 8;
    const int mr  = rg * 8;

    float acc[8][8];
    #pragma unroll
    for (int i = 0; i < 8; i++)
        #pragma unroll
        for (int j = 0; j < 8; j++) acc[i][j] = 0.0f;
    float ksum_local = 0.0f;

    const int base = blockIdx.x * CHUNK;
    const int kr0 = tid >> 5;
    const int cq  = (tid & 31) * 4;
    const int kr1 = (tid + 256) >> 5;

    for (int t = 0; t < CHUNK; t += 16) {
        const int ra = base + t + kr0;
        const int rb = base + t + kr1;
        float4 k0 = make_float4(0, 0, 0, 0), k1 = k0, v0 = k0, v1 = k0;
        if (ra < NROWS) {
            k0 = *(const float4*)(g_K + (size_t)ra * DOUT + cq);
            v0 = *(const float4*)(g_V + (size_t)ra * DOUT + cq);
        }
        if (rb < NROWS) {
            k1 = *(const float4*)(g_K + (size_t)rb * DOUT + cq);
            v1 = *(const float4*)(g_V + (size_t)rb * DOUT + cq);
        }
        __syncthreads();
        *(float4*)&Ks[kr0][cq] = k0;
        *(float4*)&Ks[kr1][cq] = k1;
        *(float4*)&Vs[kr0][cq] = v0;
        *(float4*)&Vs[kr1][cq] = v1;
        __syncthreads();

        #pragma unroll
        for (int kk = 0; kk < 16; kk++) {
            float4 ka0 = *(const float4*)&Ks[kk][mr];
            float4 ka1 = *(const float4*)&Ks[kk][mr + 4];
            float4 vb0 = *(const float4*)&Vs[kk][mc];
            float4 vb1 = *(const float4*)&Vs[kk][mc + 4];
            float kr[8] = {ka0.x, ka0.y, ka0.z, ka0.w, ka1.x, ka1.y, ka1.z, ka1.w};
            float vr[8] = {vb0.x, vb0.y, vb0.z, vb0.w, vb1.x, vb1.y, vb1.z, vb1.w};
            #pragma unroll
            for (int i = 0; i < 8; i++)
                #pragma unroll
                for (int j = 0; j < 8; j++)
                    acc[i][j] = fmaf(kr[i], vr[j], acc[i][j]);
        }

        if (tid < DOUT) {
            #pragma unroll
            for (int kk = 0; kk < 16; kk++)
                ksum_local += Ks[kk][tid];
        }
    }

    float* kvout = g_KVpart + (size_t)blockIdx.x * (DOUT * DOUT);
    #pragma unroll
    for (int i = 0; i < 8; i++) {
        float* row = kvout + (size_t)(mr + i) * DOUT + mc;
        *(float4*)(row)     = make_float4(acc[i][0], acc[i][1], acc[i][2], acc[i][3]);
        *(float4*)(row + 4) = make_float4(acc[i][4], acc[i][5], acc[i][6], acc[i][7]);
    }
    if (tid < DOUT)
        g_kspart[(size_t)blockIdx.x * DOUT + tid] = ksum_local;
}

// ============================================================================
// Reduce partials -> g_KV, g_ksum.
// ============================================================================
__global__ void reduce_kernel()
{
    const int i = blockIdx.x * blockDim.x + threadIdx.x;
    if (i < DOUT * DOUT) {
        float s = 0.0f;
        for (int b = 0; b < NB; b++)
            s += g_KVpart[(size_t)b * (DOUT * DOUT) + i];
        g_KV[i] = s;
    } else {
        const int j = i - DOUT * DOUT;
        if (j < DOUT) {
            float s = 0.0f;
            for (int b = 0; b < NB; b++)
                s += g_kspart[(size_t)b * DOUT + j];
            g_ksum[j] = s;
        }
    }
}

// ============================================================================
// Kernel C: out = elu((Q @ KV) * (1 / (Q @ ksum)))
// ============================================================================
#define SMEMC_FLOATS (DOUT * DOUT + DOUT * 68 + DOUT + 64)

__global__ __launch_bounds__(256) void out_kernel(float* __restrict__ out)
{
    extern __shared__ float smf[];
    float* KVs    = smf;
    float* Qs     = smf + DOUT * DOUT;
    float* ksum_s = Qs + DOUT * 68;
    float* z_s    = ksum_s + DOUT;

    const int tid  = threadIdx.x;
    const int row0 = blockIdx.x * 64;

    for (int i = tid; i < (DOUT * DOUT) / 4; i += 256)
        ((float4*)KVs)[i] = ((const float4*)g_KV)[i];
    if (tid < DOUT)
        ksum_s[tid] = g_ksum[tid];

    for (int i = tid; i < 2048; i += 256) {
        const int r  = i >> 5;
        const int cq = (i & 31) * 4;
        float4 q = *(const float4*)(g_Q + (size_t)(row0 + r) * DOUT + cq);
        Qs[(cq + 0) * 68 + r] = q.x;
        Qs[(cq + 1) * 68 + r] = q.y;
        Qs[(cq + 2) * 68 + r] = q.z;
        Qs[(cq + 3) * 68 + r] = q.w;
    }
    __syncthreads();

    if (tid < 64) {
        float dot = 0.0f;
        #pragma unroll 8
        for (int k = 0; k < DOUT; k++)
            dot = fmaf(Qs[k * 68 + tid], ksum_s[k], dot);
        z_s[tid] = 1.0f / dot;
    }
    __syncthreads();

    const int cg = tid & 15;
    const int rg = tid >> 4;
    const int mc = cg * 8;
    const int mr = rg * 4;

    float acc[4][8];
    #pragma unroll
    for (int i = 0; i < 4; i++)
        #pragma unroll
        for (int j = 0; j < 8; j++) acc[i][j] = 0.0f;

    #pragma unroll 8
    for (int kk = 0; kk < DOUT; kk++) {
        float4 a  = *(const float4*)&Qs[kk * 68 + mr];
        float4 b0 = *(const float4*)&KVs[kk * DOUT + mc];
        float4 b1 = *(const float4*)&KVs[kk * DOUT + mc + 4];
        float ar[4] = {a.x, a.y, a.z, a.w};
        float br[8] = {b0.x, b0.y, b0.z, b0.w, b1.x, b1.y, b1.z, b1.w};
        #pragma unroll
        for (int i = 0; i < 4; i++)
            #pragma unroll
            for (int j = 0; j < 8; j++)
                acc[i][j] = fmaf(ar[i], br[j], acc[i][j]);
    }

    #pragma unroll
    for (int i = 0; i < 4; i++) {
        const float z = z_s[mr + i];
        float v[8];
        #pragma unroll
        for (int j = 0; j < 8; j++) {
            float x = acc[i][j] * z;
            v[j] = x > 0.0f ? x : expm1f(x);
        }
        float* orow = out + (size_t)(row0 + mr + i) * DOUT + mc;
        *(float4*)(orow)     = make_float4(v[0], v[1], v[2], v[3]);
        *(float4*)(orow + 4) = make_float4(v[4], v[5], v[6], v[7]);
    }
}

// ============================================================================
// Launch
// ============================================================================
extern "C" void kernel_launch(void* const* d_in, const int* in_sizes, int n_in,
                              void* d_out, int out_size)
{
    const float* h  = (const float*)d_in[0];
    const float* Wq = (const float*)d_in[1];
    const float* Wk = (const float*)d_in[2];
    const float* Wv = (const float*)d_in[3];
    float* out = (float*)d_out;

    cudaFuncSetAttribute(qkv_mma, cudaFuncAttributeMaxDynamicSharedMemorySize, SM_QKV_TOTAL);
    const int smemC = SMEMC_FLOATS * (int)sizeof(float);
    cudaFuncSetAttribute(out_kernel, cudaFuncAttributeMaxDynamicSharedMemorySize, smemC);

    convert_w<<<(DIN * NQKV + 255) / 256, 256>>>(Wq, Wk, Wv);

    dim3 gridA(3, NBLK_M);
    qkv_mma<<<gridA, 256, SM_QKV_TOTAL>>>(h);

    kv_kernel<<<NB, 256>>>();
    reduce_kernel<<<(DOUT * DOUT + DOUT + 255) / 256, 256>>>();
    out_kernel<<<NROWS / 64, 256, smemC>>>(out);
}